// round 2
// baseline (speedup 1.0000x reference)
#include <cuda_runtime.h>
#include <cuda_bf16.h>
#include <math_constants.h>

#define D     128
#define NMET  20000
#define NRXN  50000
#define EMAX  1000000
#define SCANB 512

// ---------------- scratch (static device globals; no allocation) -------------
__device__ float g_gate[NMET];            // per-metabolite gate scalar
__device__ float g_T[NMET * D];           // per-metabolite transformed row (relu(f@Wt+bt))
__device__ int   g_cnt[NRXN];             // histogram of rxn ids
__device__ int   g_off[NRXN + 1];         // CSR offsets
__device__ int   g_cursor[NRXN];          // scatter cursors
__device__ int   g_bsum[(NRXN + SCANB - 1) / SCANB];   // scan partials
__device__ int   g_bbase[(NRXN + SCANB - 1) / SCANB];  // scan bases
__device__ int   g_sorted_met[EMAX];
__device__ float g_sorted_gate[EMAX];
__device__ int   g_is64;

// ---------------- dtype detection for hyperedge_index ------------------------
// If the buffer is int64 (values < 2^31, little-endian), every odd 32-bit word
// is zero. If int32, odd words are random metabolite ids in [0, 20000) —
// probability all 64 sampled words are zero is ~0.
__global__ void detect_kernel(const int* __restrict__ w) {
    int t  = threadIdx.x;                       // 32 threads
    int nz = (w[2 * t + 1] != 0) | (w[2 * (t + 32) + 1] != 0);
    unsigned m = __ballot_sync(0xffffffffu, nz);
    if (t == 0) g_is64 = (m == 0) ? 1 : 0;
}

__device__ __forceinline__ void load_edge(const void* idx, long long E, long long e,
                                          int is64, int& met, int& rxn) {
    if (is64) {
        const long long* p = (const long long*)idx;
        met = (int)p[e];
        rxn = (int)p[E + e];
    } else {
        const int* p = (const int*)idx;
        met = p[e];
        rxn = p[E + e];
    }
}

// ---------------- zero histogram ---------------------------------------------
__global__ void zero_cnt_kernel(int n_rxn) {
    int i = blockIdx.x * blockDim.x + threadIdx.x;
    if (i < n_rxn) g_cnt[i] = 0;
}

// ---------------- per-metabolite precompute: gate + transform ----------------
// 128 threads/block, 4 rows per iteration. Weights stream from L1 (Wt=64KB,
// W1=32KB both resident), each weight load amortized over 4 rows.
__global__ void precompute_kernel(const float* __restrict__ feats,
                                  const float* __restrict__ W1,
                                  const float* __restrict__ b1,
                                  const float* __restrict__ W2,
                                  const float* __restrict__ b2,
                                  const float* __restrict__ Wt,
                                  const float* __restrict__ bt,
                                  int n_met) {
    __shared__ float f[4][D];
    __shared__ float hred[4][64];
    int t    = threadIdx.x;
    int warp = t >> 5;
    int lane = t & 31;

    for (int row0 = blockIdx.x * 4; row0 < n_met; row0 += gridDim.x * 4) {
        int nr = n_met - row0; if (nr > 4) nr = 4;
        #pragma unroll
        for (int r = 0; r < 4; ++r)
            f[r][t] = (r < nr) ? feats[(long long)(row0 + r) * D + t] : 0.f;
        __syncthreads();

        // transform: T[row][t] = relu(sum_k f[row][k] * Wt[k][t] + bt[t])
        float btv = bt[t];
        float a0 = btv, a1 = btv, a2 = btv, a3 = btv;
        #pragma unroll 8
        for (int k = 0; k < D; ++k) {
            float w = Wt[k * D + t];
            a0 = fmaf(f[0][k], w, a0);
            a1 = fmaf(f[1][k], w, a1);
            a2 = fmaf(f[2][k], w, a2);
            a3 = fmaf(f[3][k], w, a3);
        }
        if (0 < nr) g_T[(long long)(row0 + 0) * D + t] = fmaxf(a0, 0.f);
        if (1 < nr) g_T[(long long)(row0 + 1) * D + t] = fmaxf(a1, 0.f);
        if (2 < nr) g_T[(long long)(row0 + 2) * D + t] = fmaxf(a2, 0.f);
        if (3 < nr) g_T[(long long)(row0 + 3) * D + t] = fmaxf(a3, 0.f);

        // gate hidden layer: h[row][t] = relu(sum_k f[row][k] * W1[k][t] + b1[t]), t<64
        if (t < 64) {
            float b1v = b1[t];
            float h0 = b1v, h1 = b1v, h2 = b1v, h3 = b1v;
            #pragma unroll 8
            for (int k = 0; k < D; ++k) {
                float w = W1[k * 64 + t];
                h0 = fmaf(f[0][k], w, h0);
                h1 = fmaf(f[1][k], w, h1);
                h2 = fmaf(f[2][k], w, h2);
                h3 = fmaf(f[3][k], w, h3);
            }
            float w2 = W2[t];
            hred[0][t] = fmaxf(h0, 0.f) * w2;
            hred[1][t] = fmaxf(h1, 0.f) * w2;
            hred[2][t] = fmaxf(h2, 0.f) * w2;
            hred[3][t] = fmaxf(h3, 0.f) * w2;
        }
        __syncthreads();

        // warp r reduces hred[r][0..63] -> gate scalar
        {
            float v = hred[warp][lane] + hred[warp][lane + 32];
            #pragma unroll
            for (int o = 16; o; o >>= 1) v += __shfl_xor_sync(0xffffffffu, v, o);
            if (lane == 0 && warp < nr) g_gate[row0 + warp] = v + b2[0];
        }
        __syncthreads();
    }
}

// ---------------- histogram ---------------------------------------------------
__global__ void hist_kernel(const void* __restrict__ idx, long long E) {
    int is64 = g_is64;
    long long i = (long long)blockIdx.x * blockDim.x + threadIdx.x;
    long long stride = (long long)gridDim.x * blockDim.x;
    for (long long e = i; e < E; e += stride) {
        int met, rxn;
        load_edge(idx, E, e, is64, met, rxn);
        atomicAdd(&g_cnt[rxn], 1);
    }
}

// ---------------- 3-pass exclusive scan of g_cnt ------------------------------
__global__ void scan_sums_kernel(int n_rxn) {
    __shared__ int s[SCANB];
    int g = blockIdx.x * SCANB + threadIdx.x;
    s[threadIdx.x] = (g < n_rxn) ? g_cnt[g] : 0;
    __syncthreads();
    for (int o = SCANB / 2; o; o >>= 1) {
        if (threadIdx.x < o) s[threadIdx.x] += s[threadIdx.x + o];
        __syncthreads();
    }
    if (threadIdx.x == 0) g_bsum[blockIdx.x] = s[0];
}

__global__ void scan_base_kernel(int nb, int n_rxn) {
    // single thread: nb <= 98
    int run = 0;
    for (int b = 0; b < nb; ++b) {
        g_bbase[b] = run;
        run += g_bsum[b];
    }
    g_off[n_rxn] = run;
}

__global__ void scan_final_kernel(int n_rxn) {
    __shared__ int s[SCANB];
    int g = blockIdx.x * SCANB + threadIdx.x;
    int v = (g < n_rxn) ? g_cnt[g] : 0;
    s[threadIdx.x] = v;
    __syncthreads();
    #pragma unroll
    for (int o = 1; o < SCANB; o <<= 1) {
        int add = (threadIdx.x >= o) ? s[threadIdx.x - o] : 0;
        __syncthreads();
        s[threadIdx.x] += add;
        __syncthreads();
    }
    if (g < n_rxn) {
        int excl = s[threadIdx.x] - v + g_bbase[blockIdx.x];
        g_off[g]    = excl;
        g_cursor[g] = excl;
    }
}

// ---------------- scatter: counting-sort edges by rxn --------------------------
__global__ void scatter_kernel(const void* __restrict__ idx, long long E) {
    int is64 = g_is64;
    long long i = (long long)blockIdx.x * blockDim.x + threadIdx.x;
    long long stride = (long long)gridDim.x * blockDim.x;
    for (long long e = i; e < E; e += stride) {
        int met, rxn;
        load_edge(idx, E, e, is64, met, rxn);
        int pos = atomicAdd(&g_cursor[rxn], 1);
        g_sorted_met[pos]  = met;
        g_sorted_gate[pos] = g_gate[met];
    }
}

// ---------------- per-reaction: segment softmax + weighted gather-sum ---------
// One warp per reaction. T rows are L2-resident; each edge pulls one 512B row.
__global__ void rxn_kernel(float* __restrict__ Z, int n_rxn) {
    int gwarp = (blockIdx.x * blockDim.x + threadIdx.x) >> 5;
    int lane  = threadIdx.x & 31;
    if (gwarp >= n_rxn) return;

    int beg = g_off[gwarp];
    int end = g_off[gwarp + 1];

    float4 acc = make_float4(0.f, 0.f, 0.f, 0.f);

    if (beg < end) {
        // pass 1: max
        float m = -CUDART_INF_F;
        for (int i = beg + lane; i < end; i += 32)
            m = fmaxf(m, g_sorted_gate[i]);
        #pragma unroll
        for (int o = 16; o; o >>= 1)
            m = fmaxf(m, __shfl_xor_sync(0xffffffffu, m, o));

        // pass 2: sum of exp
        float s = 0.f;
        for (int i = beg + lane; i < end; i += 32)
            s += __expf(g_sorted_gate[i] - m);
        #pragma unroll
        for (int o = 16; o; o >>= 1)
            s += __shfl_xor_sync(0xffffffffu, s, o);
        float inv = 1.f / s;

        // pass 3: weighted accumulation of T rows (all lanes cooperate per edge)
        for (int i = beg; i < end; ++i) {
            float a   = __expf(g_sorted_gate[i] - m) * inv;  // broadcast
            int   met = g_sorted_met[i];                      // broadcast
            const float4 tv =
                *(const float4*)(g_T + (long long)met * D + lane * 4);
            acc.x = fmaf(a, tv.x, acc.x);
            acc.y = fmaf(a, tv.y, acc.y);
            acc.z = fmaf(a, tv.z, acc.z);
            acc.w = fmaf(a, tv.w, acc.w);
        }
    }

    *(float4*)(Z + (long long)gwarp * D + lane * 4) = acc;
}

// ---------------- launch -------------------------------------------------------
extern "C" void kernel_launch(void* const* d_in, const int* in_sizes, int n_in,
                              void* d_out, int out_size) {
    const float* feats = (const float*)d_in[0];
    const void*  idx   = d_in[1];
    const float* W1    = (const float*)d_in[2];
    const float* b1    = (const float*)d_in[3];
    const float* W2    = (const float*)d_in[4];
    const float* b2    = (const float*)d_in[5];
    const float* Wt    = (const float*)d_in[6];
    const float* bt    = (const float*)d_in[7];
    float*       Z     = (float*)d_out;

    int       n_met = in_sizes[0] / D;
    long long E     = (long long)in_sizes[1] / 2;
    int       n_rxn = out_size / D;
    int       nb    = (n_rxn + SCANB - 1) / SCANB;

    detect_kernel<<<1, 32>>>((const int*)idx);
    zero_cnt_kernel<<<(n_rxn + 255) / 256, 256>>>(n_rxn);
    precompute_kernel<<<320, 128>>>(feats, W1, b1, W2, b2, Wt, bt, n_met);
    hist_kernel<<<2048, 256>>>(idx, E);
    scan_sums_kernel<<<nb, SCANB>>>(n_rxn);
    scan_base_kernel<<<1, 1>>>(nb, n_rxn);
    scan_final_kernel<<<nb, SCANB>>>(n_rxn);
    scatter_kernel<<<2048, 256>>>(idx, E);
    {
        int threads = 256;
        int warps_per_block = threads / 32;
        int blocks = (n_rxn + warps_per_block - 1) / warps_per_block;
        rxn_kernel<<<blocks, threads>>>(Z, n_rxn);
    }
}

// round 3
// speedup vs baseline: 1.6402x; 1.6402x over previous
#include <cuda_runtime.h>
#include <cuda_fp16.h>
#include <math_constants.h>

#define D     128
#define NMET  20000
#define NRXN  50000
#define EMAX  1000000
#define SCANB 512

// ---------------- scratch (static device globals; no allocation) -------------
__device__ float  g_exp[NMET];             // exp(gate) per metabolite
__device__ __half g_Th[NMET * D];          // transformed rows in fp16
__device__ int    g_cnt[NRXN];
__device__ int    g_off[NRXN + 1];
__device__ int    g_cursor[NRXN];
__device__ int    g_bsum[(NRXN + SCANB - 1) / SCANB];
__device__ int    g_bbase[(NRXN + SCANB - 1) / SCANB];
__device__ float2 g_pair[EMAX];            // {met-as-float-bits, exp(gate)} sorted by rxn
__device__ int    g_is64;

// ---------------- init: zero histogram + detect index dtype -------------------
// int64 little-endian with values < 2^31 -> every odd 32-bit word is zero.
__global__ void init_kernel(const int* __restrict__ w, int n_rxn) {
    int i = blockIdx.x * blockDim.x + threadIdx.x;
    if (i < n_rxn) g_cnt[i] = 0;
    if (blockIdx.x == 0 && threadIdx.x < 32) {
        int t  = threadIdx.x;
        int nz = (w[2 * t + 1] != 0) | (w[2 * (t + 32) + 1] != 0);
        unsigned m = __ballot_sync(0xffffffffu, nz);
        if (t == 0) g_is64 = (m == 0) ? 1 : 0;
    }
}

// ---------------- per-metabolite precompute: exp(gate) + fp16 transform -------
__global__ void precompute_kernel(const float* __restrict__ feats,
                                  const float* __restrict__ W1,
                                  const float* __restrict__ b1,
                                  const float* __restrict__ W2,
                                  const float* __restrict__ b2,
                                  const float* __restrict__ Wt,
                                  const float* __restrict__ bt,
                                  int n_met) {
    __shared__ float f[4][D];
    __shared__ float hred[4][64];
    int t    = threadIdx.x;
    int warp = t >> 5;
    int lane = t & 31;

    int row0 = blockIdx.x * 4;
    if (row0 >= n_met) return;
    int nr = n_met - row0; if (nr > 4) nr = 4;

    #pragma unroll
    for (int r = 0; r < 4; ++r)
        f[r][t] = (r < nr) ? feats[(long long)(row0 + r) * D + t] : 0.f;
    __syncthreads();

    // transform: T[row][t] = relu(sum_k f[row][k] * Wt[k][t] + bt[t]) -> fp16
    float btv = bt[t];
    float a0 = btv, a1 = btv, a2 = btv, a3 = btv;
    #pragma unroll 8
    for (int k = 0; k < D; ++k) {
        float w = Wt[k * D + t];
        a0 = fmaf(f[0][k], w, a0);
        a1 = fmaf(f[1][k], w, a1);
        a2 = fmaf(f[2][k], w, a2);
        a3 = fmaf(f[3][k], w, a3);
    }
    if (0 < nr) g_Th[(long long)(row0 + 0) * D + t] = __float2half(fmaxf(a0, 0.f));
    if (1 < nr) g_Th[(long long)(row0 + 1) * D + t] = __float2half(fmaxf(a1, 0.f));
    if (2 < nr) g_Th[(long long)(row0 + 2) * D + t] = __float2half(fmaxf(a2, 0.f));
    if (3 < nr) g_Th[(long long)(row0 + 3) * D + t] = __float2half(fmaxf(a3, 0.f));

    // gate hidden layer (t < 64)
    if (t < 64) {
        float b1v = b1[t];
        float h0 = b1v, h1 = b1v, h2 = b1v, h3 = b1v;
        #pragma unroll 8
        for (int k = 0; k < D; ++k) {
            float w = W1[k * 64 + t];
            h0 = fmaf(f[0][k], w, h0);
            h1 = fmaf(f[1][k], w, h1);
            h2 = fmaf(f[2][k], w, h2);
            h3 = fmaf(f[3][k], w, h3);
        }
        float w2 = W2[t];
        hred[0][t] = fmaxf(h0, 0.f) * w2;
        hred[1][t] = fmaxf(h1, 0.f) * w2;
        hred[2][t] = fmaxf(h2, 0.f) * w2;
        hred[3][t] = fmaxf(h3, 0.f) * w2;
    }
    __syncthreads();

    // warp r reduces hred[r][0..63] -> gate scalar -> store exp(gate)
    float v = hred[warp][lane] + hred[warp][lane + 32];
    #pragma unroll
    for (int o = 16; o; o >>= 1) v += __shfl_xor_sync(0xffffffffu, v, o);
    if (lane == 0 && warp < nr) g_exp[row0 + warp] = __expf(v + b2[0]);
}

// ---------------- histogram (reads only the rxn half, 2 edges/thread) ---------
__global__ void hist_kernel(const void* __restrict__ idx, long long E) {
    int is64 = g_is64;
    long long np = E >> 1;
    long long i = (long long)blockIdx.x * blockDim.x + threadIdx.x;
    long long stride = (long long)gridDim.x * blockDim.x;
    if (is64) {
        const longlong2* r = (const longlong2*)((const long long*)idx + E);
        for (long long p = i; p < np; p += stride) {
            longlong2 v = r[p];
            atomicAdd(&g_cnt[(int)v.x], 1);
            atomicAdd(&g_cnt[(int)v.y], 1);
        }
        if (i == 0 && (E & 1))
            atomicAdd(&g_cnt[(int)((const long long*)idx)[E + E - 1]], 1);
    } else {
        const int2* r = (const int2*)((const int*)idx + E);
        for (long long p = i; p < np; p += stride) {
            int2 v = r[p];
            atomicAdd(&g_cnt[v.x], 1);
            atomicAdd(&g_cnt[v.y], 1);
        }
        if (i == 0 && (E & 1))
            atomicAdd(&g_cnt[((const int*)idx)[E + E - 1]], 1);
    }
}

// ---------------- 3-pass exclusive scan of g_cnt ------------------------------
__global__ void scan_sums_kernel(int n_rxn) {
    __shared__ int s[SCANB];
    int g = blockIdx.x * SCANB + threadIdx.x;
    s[threadIdx.x] = (g < n_rxn) ? g_cnt[g] : 0;
    __syncthreads();
    for (int o = SCANB / 2; o; o >>= 1) {
        if (threadIdx.x < o) s[threadIdx.x] += s[threadIdx.x + o];
        __syncthreads();
    }
    if (threadIdx.x == 0) g_bsum[blockIdx.x] = s[0];
}

__global__ void scan_base_kernel(int nb, int n_rxn) {
    int run = 0;
    for (int b = 0; b < nb; ++b) {
        g_bbase[b] = run;
        run += g_bsum[b];
    }
    g_off[n_rxn] = run;
}

__global__ void scan_final_kernel(int n_rxn) {
    __shared__ int s[SCANB];
    int g = blockIdx.x * SCANB + threadIdx.x;
    int v = (g < n_rxn) ? g_cnt[g] : 0;
    s[threadIdx.x] = v;
    __syncthreads();
    #pragma unroll
    for (int o = 1; o < SCANB; o <<= 1) {
        int add = (threadIdx.x >= o) ? s[threadIdx.x - o] : 0;
        __syncthreads();
        s[threadIdx.x] += add;
        __syncthreads();
    }
    if (g < n_rxn) {
        int excl = s[threadIdx.x] - v + g_bbase[blockIdx.x];
        g_off[g]    = excl;
        g_cursor[g] = excl;
    }
}

// ---------------- scatter: counting-sort {met, exp(gate)} by rxn --------------
__device__ __forceinline__ void scatter_one(int met, int rxn) {
    int pos = atomicAdd(&g_cursor[rxn], 1);
    g_pair[pos] = make_float2(__int_as_float(met), g_exp[met]);
}

__global__ void scatter_kernel(const void* __restrict__ idx, long long E) {
    int is64 = g_is64;
    long long np = E >> 1;
    long long i = (long long)blockIdx.x * blockDim.x + threadIdx.x;
    long long stride = (long long)gridDim.x * blockDim.x;
    if (is64) {
        const longlong2* mv = (const longlong2*)idx;
        const longlong2* rv = (const longlong2*)((const long long*)idx + E);
        for (long long p = i; p < np; p += stride) {
            longlong2 m = mv[p];
            longlong2 r = rv[p];
            scatter_one((int)m.x, (int)r.x);
            scatter_one((int)m.y, (int)r.y);
        }
        if (i == 0 && (E & 1))
            scatter_one((int)((const long long*)idx)[E - 1],
                        (int)((const long long*)idx)[E + E - 1]);
    } else {
        const int2* mv = (const int2*)idx;
        const int2* rv = (const int2*)((const int*)idx + E);
        for (long long p = i; p < np; p += stride) {
            int2 m = mv[p];
            int2 r = rv[p];
            scatter_one(m.x, r.x);
            scatter_one(m.y, r.y);
        }
        if (i == 0 && (E & 1))
            scatter_one(((const int*)idx)[E - 1], ((const int*)idx)[E + E - 1]);
    }
}

// ---------------- per-reaction: softmax-weighted gather-sum -------------------
// One warp per reaction. exp(gate) is presummed; T rows are fp16, L2-resident.
__device__ __forceinline__ void acc_row(float4& acc, float w, int met, int lane) {
    uint2 raw = *(const uint2*)(g_Th + (long long)met * D + lane * 4);
    __half2 h0 = *reinterpret_cast<const __half2*>(&raw.x);
    __half2 h1 = *reinterpret_cast<const __half2*>(&raw.y);
    float2 f0 = __half22float2(h0);
    float2 f1 = __half22float2(h1);
    acc.x = fmaf(w, f0.x, acc.x);
    acc.y = fmaf(w, f0.y, acc.y);
    acc.z = fmaf(w, f1.x, acc.z);
    acc.w = fmaf(w, f1.y, acc.w);
}

__global__ void rxn_kernel(float* __restrict__ Z, int n_rxn) {
    int gw   = (blockIdx.x * blockDim.x + threadIdx.x) >> 5;
    int lane = threadIdx.x & 31;
    if (gw >= n_rxn) return;

    int beg = g_off[gw];
    int end = g_off[gw + 1];

    float4 acc = make_float4(0.f, 0.f, 0.f, 0.f);

    if (beg < end) {
        // pass 1: sum of exp(gate)
        float s = 0.f;
        for (int i = beg + lane; i < end; i += 32) s += g_pair[i].y;
        #pragma unroll
        for (int o = 16; o; o >>= 1) s += __shfl_xor_sync(0xffffffffu, s, o);
        float inv = 1.f / s;

        // pass 2: weighted accumulate, unrolled x2 for MLP
        int i = beg;
        for (; i + 2 <= end; i += 2) {
            float2 pa = g_pair[i];
            float2 pb = g_pair[i + 1];
            acc_row(acc, pa.y * inv, __float_as_int(pa.x), lane);
            acc_row(acc, pb.y * inv, __float_as_int(pb.x), lane);
        }
        if (i < end) {
            float2 pa = g_pair[i];
            acc_row(acc, pa.y * inv, __float_as_int(pa.x), lane);
        }
    }

    *(float4*)(Z + (long long)gw * D + lane * 4) = acc;
}

// ---------------- launch -------------------------------------------------------
extern "C" void kernel_launch(void* const* d_in, const int* in_sizes, int n_in,
                              void* d_out, int out_size) {
    const float* feats = (const float*)d_in[0];
    const void*  idx   = d_in[1];
    const float* W1    = (const float*)d_in[2];
    const float* b1    = (const float*)d_in[3];
    const float* W2    = (const float*)d_in[4];
    const float* b2    = (const float*)d_in[5];
    const float* Wt    = (const float*)d_in[6];
    const float* bt    = (const float*)d_in[7];
    float*       Z     = (float*)d_out;

    int       n_met = in_sizes[0] / D;
    long long E     = (long long)in_sizes[1] / 2;
    int       n_rxn = out_size / D;
    int       nb    = (n_rxn + SCANB - 1) / SCANB;

    init_kernel<<<(n_rxn + 255) / 256, 256>>>((const int*)idx, n_rxn);
    precompute_kernel<<<(n_met + 3) / 4, 128>>>(feats, W1, b1, W2, b2, Wt, bt, n_met);
    hist_kernel<<<1024, 256>>>(idx, E);
    scan_sums_kernel<<<nb, SCANB>>>(n_rxn);
    scan_base_kernel<<<1, 1>>>(nb, n_rxn);
    scan_final_kernel<<<nb, SCANB>>>(n_rxn);
    scatter_kernel<<<1024, 256>>>(idx, E);
    {
        int threads = 256;
        int blocks  = (n_rxn + 7) / 8;
        rxn_kernel<<<blocks, threads>>>(Z, n_rxn);
    }
}